// round 8
// baseline (speedup 1.0000x reference)
#include <cuda_runtime.h>
#include <cuda_bf16.h>
#include <cstdint>

#define HH      1024
#define NMODES  64
#define LLEN    2048
#define TPB     256
#define GRID    512          // 2 heads per CTA, sequential

// smem layout (dynamic):
//  Asm: 32 x 132 u32   A'[a][k], k=2n: Re(c*z64^a), k=2n+1: Im(c*z64^a)
//  Bt : 64 x 132 u32   Bt[b][k], k=2n: Re(z^b),     k=2n+1: -Im(z^b)
//  SC : 64 x 13 f32    per-mode consts {z, z16, z64, z512, Cmod}
#define A_STRIDE 132
#define B_STRIDE 132
#define SC_STRIDE 13
#define A_WORDS  (32 * A_STRIDE)
#define B_WORDS  (64 * B_STRIDE)
#define SC_WORDS (64 * SC_STRIDE)
#define SMEM_BYTES ((A_WORDS + B_WORDS + SC_WORDS) * 4)

__device__ __forceinline__ uint32_t tf32c(float f) {
    uint32_t r; asm("cvt.rna.tf32.f32 %0,%1;" : "=r"(r) : "f"(f)); return r;
}

__device__ __forceinline__ void sts_v2(uint32_t addr, uint32_t a, uint32_t b) {
    asm volatile("st.shared.v2.u32 [%0],{%1,%2};" :: "r"(addr), "r"(a), "r"(b) : "memory");
}

__device__ __forceinline__ uint32_t smem_u32(const void* p) {
    uint32_t a;
    asm("{ .reg .u64 t; cvta.to.shared.u64 t, %1; cvt.u32.u64 %0, t; }" : "=r"(a) : "l"(p));
    return a;
}

__device__ __forceinline__ void mma8(float* d,
                                     uint32_t a0, uint32_t a1, uint32_t a2, uint32_t a3,
                                     uint32_t b0, uint32_t b1) {
    asm volatile(
        "mma.sync.aligned.m16n8k8.row.col.f32.tf32.tf32.f32 "
        "{%0,%1,%2,%3},{%4,%5,%6,%7},{%8,%9},{%0,%1,%2,%3};"
        : "+f"(d[0]), "+f"(d[1]), "+f"(d[2]), "+f"(d[3])
        : "r"(a0), "r"(a1), "r"(a2), "r"(a3), "r"(b0), "r"(b1));
}

__global__ __launch_bounds__(TPB, 4)
void ssd_tc_v8_kernel(
    const float* __restrict__ log_dt,
    const float* __restrict__ log_w_real,
    const float* __restrict__ w_imag,
    const float* __restrict__ C_re,
    const float* __restrict__ C_im,
    float* __restrict__ out)
{
    extern __shared__ char smem_raw[];
    uint32_t* Asm = reinterpret_cast<uint32_t*>(smem_raw);
    uint32_t* Bt  = Asm + A_WORDS;
    float*    SC  = reinterpret_cast<float*>(Bt + B_WORDS);

    const int tid  = threadIdx.x;
    const int lane = tid & 31;
    const int warp = tid >> 5;
    const int n    = tid & 63;     // mode
    const int q    = tid >> 6;     // quarter 0..3
    const int r4   = lane >> 2;    // 0..7
    const int c4   = lane & 3;     // 0..3

    const uint32_t aA = smem_u32(Asm);
    const uint32_t aB = smem_u32(Bt);

    // exponent scale per quarter: {1, 16, 64, 512}
    const float scale = (q == 0) ? 1.0f : (q == 1) ? 16.0f : (q == 2) ? 64.0f : 512.0f;

    for (int rep = 0; rep < 2; rep++) {
        const int h = blockIdx.x * 2 + rep;

        // ---------- Phase 1: thread (n,q) computes z^scale; q=0 also Cmod ----------
        {
            const float dt = expf(log_dt[h]);
            const float wr = -expf(log_w_real[h * NMODES + n]);
            const float wi = w_imag[h * NMODES + n];
            const float ar = wr * dt;
            const float ai = wi * dt;

            float s, c;
            const float e = expf(ar * scale);
            sincosf(ai * scale, &s, &c);   // power-of-2 scaled arg: exact fp32 product
            float* sc = SC + n * SC_STRIDE;
            sc[2 * q]     = e * c;
            sc[2 * q + 1] = e * s;

            if (q == 0) {
                const float zr = e * c, zi = e * s;
                // 2*Cmod = 2*C*(z-1)/w
                const float den = wr * wr + wi * wi;
                const float zm  = zr - 1.0f;
                const float tr  = (zm * wr + zi * wi) / den;
                const float ti  = (zi * wr - zm * wi) / den;
                const float cre = C_re[h * NMODES + n];
                const float cim = C_im[h * NMODES + n];
                sc[8] = 2.0f * (cre * tr - cim * ti);
                sc[9] = 2.0f * (cre * ti + cim * tr);
            }
        }
        __syncthreads();

        // ---------- Phase 2: A rows [8q, 8q+8): c*z64^a, seeded by c*(z512)^q ----------
        {
            const float* sc = SC + n * SC_STRIDE;
            const float z64r = sc[4], z64i = sc[5];
            const float z512r = sc[6], z512i = sc[7];
            float ur = sc[8], ui = sc[9];
            #pragma unroll 1
            for (int t = 0; t < q; t++) {
                const float tt = ur * z512r - ui * z512i;
                ui = ur * z512i + ui * z512r; ur = tt;
            }
            uint32_t addr = aA + ((q * 8) * A_STRIDE + 2 * n) * 4;
            #pragma unroll
            for (int a = 0; a < 8; a++) {
                sts_v2(addr, tf32c(ur), tf32c(ui));
                const float t = ur * z64r - ui * z64i;
                ui = ur * z64i + ui * z64r; ur = t;
                addr += A_STRIDE * 4;
            }
        }

        // ---------- Phase 3: B rows [16q, 16q+16): z^b, seeded by (z16)^q ----------
        {
            const float* sc = SC + n * SC_STRIDE;
            const float zr = sc[0], zi = sc[1];
            const float z16r = sc[2], z16i = sc[3];
            float vr = 1.0f, vi = 0.0f;
            #pragma unroll 1
            for (int t = 0; t < q; t++) {
                const float tt = vr * z16r - vi * z16i;
                vi = vr * z16i + vi * z16r; vr = tt;
            }
            uint32_t addr = aB + ((q * 16) * B_STRIDE + 2 * n) * 4;
            #pragma unroll
            for (int j = 0; j < 16; j++) {
                sts_v2(addr, tf32c(vr), tf32c(-vi));
                const float t = vr * zr - vi * zi;
                vi = vr * zi + vi * zr; vr = t;
                addr += B_STRIDE * 4;
            }
        }
        __syncthreads();

        // ---------- Phase 4: GEMM 32x64x128, 8 warps = 2(m) x 4(n), warp: m16 x n16 ----------
        const int wm = warp & 1;    // m-tile
        const int wn = warp >> 1;   // n-group (16 cols)

        float acc[8];
        #pragma unroll
        for (int i = 0; i < 8; i++) acc[i] = 0.0f;

        const uint32_t* A0 = Asm + (16 * wm + r4) * A_STRIDE + c4;
        const uint32_t* B0 = Bt + (16 * wn + r4) * B_STRIDE + c4;

        #pragma unroll
        for (int kk = 0; kk < 16; kk++) {
            const uint32_t* Ak = A0 + kk * 8;
            const uint32_t a00 = Ak[0];
            const uint32_t a01 = Ak[8 * A_STRIDE];
            const uint32_t a02 = Ak[4];
            const uint32_t a03 = Ak[8 * A_STRIDE + 4];

            const uint32_t* Bk = B0 + kk * 8;
            const uint32_t b00 = Bk[0];
            const uint32_t b01 = Bk[4];
            const uint32_t b10 = Bk[8 * B_STRIDE];
            const uint32_t b11 = Bk[8 * B_STRIDE + 4];

            mma8(acc + 0, a00, a01, a02, a03, b00, b01);   // n-tile 0
            mma8(acc + 4, a00, a01, a02, a03, b10, b11);   // n-tile 1
        }

        // ---------- Phase 5: store (l = 64*a + b) ----------
        float* op = out + (size_t)h * LLEN;
        #pragma unroll
        for (int nt = 0; nt < 2; nt++) {
            const float* a = acc + nt * 4;
            const int row = 16 * wm + r4;
            const int col = 16 * wn + 8 * nt + 2 * c4;
            *reinterpret_cast<float2*>(op + row * 64 + col)       = make_float2(a[0], a[1]);
            *reinterpret_cast<float2*>(op + (row + 8) * 64 + col) = make_float2(a[2], a[3]);
        }
        __syncthreads();   // protect smem reuse by next rep
    }
}

extern "C" void kernel_launch(void* const* d_in, const int* in_sizes, int n_in,
                              void* d_out, int out_size)
{
    const float* log_dt     = (const float*)d_in[0];
    const float* log_w_real = (const float*)d_in[1];
    const float* w_imag     = (const float*)d_in[2];
    const float* C_re       = (const float*)d_in[3];
    const float* C_im       = (const float*)d_in[4];
    float*       out        = (float*)d_out;

    cudaFuncSetAttribute(ssd_tc_v8_kernel,
                         cudaFuncAttributeMaxDynamicSharedMemorySize, SMEM_BYTES);
    ssd_tc_v8_kernel<<<GRID, TPB, SMEM_BYTES>>>(log_dt, log_w_real, w_imag, C_re, C_im, out);
}

// round 9
// speedup vs baseline: 1.0601x; 1.0601x over previous
#include <cuda_runtime.h>
#include <cstdint>

#define HH      1024
#define NMODES  64
#define LLEN    2048
#define TPB     128
#define GRID    512          // 2 heads per CTA, sequential

// smem (dynamic):
//  Apack[kk(16)][mt(2)][slot(32)] : uint4  = 16 KB   (A fragments, swizzled slots)
//  Bpack[kk(16)][nt(8)][slot(32)] : uint2  = 32 KB   (B fragments, swizzled slots)
//  SC[64][13] f32 per-mode consts {z, z32, z64, z512, 2*Cmod}
#define A_BYTES   16384
#define B_BYTES   32768
#define SC_STRIDE 13
#define SMEM_BYTES (A_BYTES + B_BYTES + NMODES * SC_STRIDE * 4)

__device__ __forceinline__ uint32_t tf32c(float f) {
    uint32_t r; asm("cvt.rna.tf32.f32 %0,%1;" : "=r"(r) : "f"(f)); return r;
}
__device__ __forceinline__ uint32_t smem_u32(const void* p) {
    uint32_t a;
    asm("{ .reg .u64 t; cvta.to.shared.u64 t, %1; cvt.u32.u64 %0, t; }" : "=r"(a) : "l"(p));
    return a;
}
__device__ __forceinline__ void sts128(uint32_t a, uint32_t x, uint32_t y, uint32_t z, uint32_t w) {
    asm volatile("st.shared.v4.u32 [%0],{%1,%2,%3,%4};" :: "r"(a), "r"(x), "r"(y), "r"(z), "r"(w) : "memory");
}
__device__ __forceinline__ void sts64(uint32_t a, uint32_t x, uint32_t y) {
    asm volatile("st.shared.v2.u32 [%0],{%1,%2};" :: "r"(a), "r"(x), "r"(y) : "memory");
}
__device__ __forceinline__ void lds128(uint32_t a, uint32_t& x, uint32_t& y, uint32_t& z, uint32_t& w) {
    asm volatile("ld.shared.v4.u32 {%0,%1,%2,%3},[%4];" : "=r"(x), "=r"(y), "=r"(z), "=r"(w) : "r"(a));
}
__device__ __forceinline__ void lds64(uint32_t a, uint32_t& x, uint32_t& y) {
    asm volatile("ld.shared.v2.u32 {%0,%1},[%2];" : "=r"(x), "=r"(y) : "r"(a));
}
__device__ __forceinline__ void mma8(float* d,
                                     uint32_t a0, uint32_t a1, uint32_t a2, uint32_t a3,
                                     uint32_t b0, uint32_t b1) {
    asm volatile(
        "mma.sync.aligned.m16n8k8.row.col.f32.tf32.tf32.f32 "
        "{%0,%1,%2,%3},{%4,%5,%6,%7},{%8,%9},{%0,%1,%2,%3};"
        : "+f"(d[0]), "+f"(d[1]), "+f"(d[2]), "+f"(d[3])
        : "r"(a0), "r"(a1), "r"(a2), "r"(a3), "r"(b0), "r"(b1));
}

__global__ __launch_bounds__(TPB, 4)
void ssd_tc_v9_kernel(
    const float* __restrict__ log_dt,
    const float* __restrict__ log_w_real,
    const float* __restrict__ w_imag,
    const float* __restrict__ C_re,
    const float* __restrict__ C_im,
    float* __restrict__ out)
{
    extern __shared__ __align__(16) char smem_raw[];
    const uint32_t aA = smem_u32(smem_raw);
    const uint32_t aB = aA + A_BYTES;
    float* SC = reinterpret_cast<float*>(smem_raw + A_BYTES + B_BYTES);

    const int tid  = threadIdx.x;
    const int lane = tid & 31;
    const int warp = tid >> 5;
    const int n    = tid & 63;     // mode
    const int half = tid >> 6;     // 0/1
    const int r4   = lane >> 2;
    const int c4   = lane & 3;

    const int n3  = n & 3;
    const int kkn = n >> 2;        // this mode's k-group
    const int kx  = kkn & 1;       // swizzle parity

    for (int rep = 0; rep < 2; rep++) {
        const int h = blockIdx.x * 2 + rep;

        // ---------- Phase 1: per-mode constants (64 threads) ----------
        if (tid < NMODES) {
            const float dt = expf(log_dt[h]);
            const float wr = -expf(log_w_real[h * NMODES + n]);
            const float wi = w_imag[h * NMODES + n];
            const float ar = wr * dt;
            const float ai = wi * dt;

            float s, c;
            const float ez = expf(ar);
            sincosf(ai, &s, &c);
            const float zr = ez * c, zi = ez * s;

            // 2*Cmod = 2*C*(z-1)/w
            const float den = wr * wr + wi * wi;
            const float zm  = zr - 1.0f;
            const float tr  = (zm * wr + zi * wi) / den;
            const float ti  = (zi * wr - zm * wi) / den;
            const float cre = C_re[h * NMODES + n];
            const float cim = C_im[h * NMODES + n];

            // z^32, z^64, z^512 (power-of-2 scaled phase args are exact fp32)
            float s32, c32, s64, c64, s512, c512;
            const float e32  = expf(ar * 32.0f);  sincosf(ai * 32.0f,  &s32,  &c32);
            const float e64  = expf(ar * 64.0f);  sincosf(ai * 64.0f,  &s64,  &c64);
            const float e512 = expf(ar * 512.0f); sincosf(ai * 512.0f, &s512, &c512);

            float* sc = SC + n * SC_STRIDE;
            sc[0] = zr;           sc[1] = zi;
            sc[2] = e32 * c32;    sc[3] = e32 * s32;
            sc[4] = e64 * c64;    sc[5] = e64 * s64;
            sc[6] = e512 * c512;  sc[7] = e512 * s512;
            sc[8] = 2.0f * (cre * tr - cim * ti);
            sc[9] = 2.0f * (cre * ti + cim * tr);
        }
        __syncthreads();

        // ---------- Phase 2: A fragments. Dual chains rows (a, a+8), a=16h+s ----------
        {
            const float* sc = SC + n * SC_STRIDE;
            const float z64r = sc[4], z64i = sc[5];
            const float z512r = sc[6], z512i = sc[7];
            float u1r = sc[8], u1i = sc[9];
            if (half) {  // x z^1024 = (z512)^2
                float t = u1r * z512r - u1i * z512i; u1i = u1r * z512i + u1i * z512r; u1r = t;
                t       = u1r * z512r - u1i * z512i; u1i = u1r * z512i + u1i * z512r; u1r = t;
            }
            float u2r = u1r * z512r - u1i * z512i;   // chain2 = chain1 * z512 (rows +8)
            float u2i = u1r * z512i + u1i * z512r;

            const uint32_t baseA = aA + (uint32_t)(kkn * 2 + half) * 512 + (uint32_t)n3 * 16;
            #pragma unroll
            for (int s = 0; s < 8; s++) {
                const uint32_t addr = baseA + (uint32_t)(s ^ kx) * 64;
                sts128(addr, tf32c(u1r), tf32c(u2r), tf32c(u1i), tf32c(u2i));
                float t = u1r * z64r - u1i * z64i; u1i = u1r * z64i + u1i * z64r; u1r = t;
                t       = u2r * z64r - u2i * z64i; u2i = u2r * z64i + u2i * z64r; u2r = t;
            }
        }

        // ---------- Phase 3: B fragments. b = 32h + j, j=0..31 ----------
        {
            const float* sc = SC + n * SC_STRIDE;
            const float zr = sc[0], zi = sc[1];
            float vr = 1.0f, vi = 0.0f;
            if (half) { vr = sc[2]; vi = sc[3]; }   // z^32
            const uint32_t baseB = aB + (uint32_t)kkn * 2048 + (uint32_t)(half * 4) * 256 + (uint32_t)n3 * 8;
            #pragma unroll
            for (int j = 0; j < 32; j++) {
                const uint32_t addr = baseB + (uint32_t)(j >> 3) * 256 + (uint32_t)((j & 7) ^ kx) * 32;
                sts64(addr, tf32c(vr), tf32c(-vi));
                const float t = vr * zr - vi * zi; vi = vr * zi + vi * zr; vr = t;
            }
        }
        __syncthreads();

        // ---------- Phase 4: GEMM 32x64x128; warp w: n-cols [16w,16w+16), all m ----------
        float acc[16];
        #pragma unroll
        for (int i = 0; i < 16; i++) acc[i] = 0.0f;

        const uint32_t rdA = aA + (uint32_t)lane * 16;
        const uint32_t rdB = aB + (uint32_t)(warp * 2) * 256 + (uint32_t)lane * 8;

        #pragma unroll
        for (int kk = 0; kk < 16; kk++) {
            const uint32_t swA = (uint32_t)(kk & 1) << 6;   // slot bit2 -> 64B (A)
            const uint32_t swB = (uint32_t)(kk & 1) << 5;   // slot bit2 -> 32B (B)

            uint32_t a00, a01, a02, a03, a10, a11, a12, a13;
            lds128((rdA ^ swA) + (uint32_t)kk * 1024,       a00, a01, a02, a03);
            lds128((rdA ^ swA) + (uint32_t)kk * 1024 + 512, a10, a11, a12, a13);

            uint32_t b00, b01, b10, b11;
            lds64((rdB ^ swB) + (uint32_t)kk * 2048,        b00, b01);
            lds64((rdB ^ swB) + (uint32_t)kk * 2048 + 256,  b10, b11);

            mma8(acc + 0,  a00, a01, a02, a03, b00, b01);
            mma8(acc + 4,  a00, a01, a02, a03, b10, b11);
            mma8(acc + 8,  a10, a11, a12, a13, b00, b01);
            mma8(acc + 12, a10, a11, a12, a13, b10, b11);
        }

        // ---------- Phase 5: store (l = 64*a + b) ----------
        float* op = out + (size_t)h * LLEN;
        #pragma unroll
        for (int mt = 0; mt < 2; mt++) {
            #pragma unroll
            for (int nt = 0; nt < 2; nt++) {
                const float* a = acc + (mt * 2 + nt) * 4;
                const int row = 16 * mt + r4;
                const int col = 16 * warp + 8 * nt + 2 * c4;
                *reinterpret_cast<float2*>(op + row * 64 + col)       = make_float2(a[0], a[1]);
                *reinterpret_cast<float2*>(op + (row + 8) * 64 + col) = make_float2(a[2], a[3]);
            }
        }
        __syncthreads();   // smem reuse by next rep
    }
}

extern "C" void kernel_launch(void* const* d_in, const int* in_sizes, int n_in,
                              void* d_out, int out_size)
{
    const float* log_dt     = (const float*)d_in[0];
    const float* log_w_real = (const float*)d_in[1];
    const float* w_imag     = (const float*)d_in[2];
    const float* C_re       = (const float*)d_in[3];
    const float* C_im       = (const float*)d_in[4];
    float*       out        = (float*)d_out;

    cudaFuncSetAttribute(ssd_tc_v9_kernel,
                         cudaFuncAttributeMaxDynamicSharedMemorySize, SMEM_BYTES);
    ssd_tc_v9_kernel<<<GRID, TPB, SMEM_BYTES>>>(log_dt, log_w_real, w_imag, C_re, C_im, out);
}

// round 10
// speedup vs baseline: 1.0721x; 1.0113x over previous
#include <cuda_runtime.h>
#include <cstdint>

#define HH      1024
#define NMODES  64
#define LLEN    2048
#define TPB     128
#define GRID    512          // 2 heads per CTA, sequential + pipelined consts

// smem (dynamic):
//  Apack[kk(16)][mt(2)][slot(32)] : uint4  = 16 KB
//  Bpack[kk(16)][nt(8)][slot(32)] : uint2  = 32 KB
#define A_BYTES   16384
#define B_BYTES   32768
#define SMEM_BYTES (A_BYTES + B_BYTES)

__device__ __forceinline__ uint32_t tf32c(float f) {
    uint32_t r; asm("cvt.rna.tf32.f32 %0,%1;" : "=r"(r) : "f"(f)); return r;
}
__device__ __forceinline__ uint32_t smem_u32(const void* p) {
    uint32_t a;
    asm("{ .reg .u64 t; cvta.to.shared.u64 t, %1; cvt.u32.u64 %0, t; }" : "=r"(a) : "l"(p));
    return a;
}
__device__ __forceinline__ void sts128(uint32_t a, uint32_t x, uint32_t y, uint32_t z, uint32_t w) {
    asm volatile("st.shared.v4.u32 [%0],{%1,%2,%3,%4};" :: "r"(a), "r"(x), "r"(y), "r"(z), "r"(w) : "memory");
}
__device__ __forceinline__ void sts64(uint32_t a, uint32_t x, uint32_t y) {
    asm volatile("st.shared.v2.u32 [%0],{%1,%2};" :: "r"(a), "r"(x), "r"(y) : "memory");
}
__device__ __forceinline__ void lds128(uint32_t a, uint32_t& x, uint32_t& y, uint32_t& z, uint32_t& w) {
    asm volatile("ld.shared.v4.u32 {%0,%1,%2,%3},[%4];" : "=r"(x), "=r"(y), "=r"(z), "=r"(w) : "r"(a));
}
__device__ __forceinline__ void lds64(uint32_t a, uint32_t& x, uint32_t& y) {
    asm volatile("ld.shared.v2.u32 {%0,%1},[%2];" : "=r"(x), "=r"(y) : "r"(a));
}
__device__ __forceinline__ void mma8(float* d,
                                     uint32_t a0, uint32_t a1, uint32_t a2, uint32_t a3,
                                     uint32_t b0, uint32_t b1) {
    asm volatile(
        "mma.sync.aligned.m16n8k8.row.col.f32.tf32.tf32.f32 "
        "{%0,%1,%2,%3},{%4,%5,%6,%7},{%8,%9},{%0,%1,%2,%3};"
        : "+f"(d[0]), "+f"(d[1]), "+f"(d[2]), "+f"(d[3])
        : "r"(a0), "r"(a1), "r"(a2), "r"(a3), "r"(b0), "r"(b1));
}

struct Consts {
    float zr, zi;          // z
    float z16r, z16i;
    float z32r, z32i;
    float z64r, z64i;
    float z512r, z512i;
    float u1r, u1i;        // A seed: 2*Cmod (half0) or 2*Cmod*z^1024 (half1)
};

__device__ __forceinline__ Consts compute_consts(
    const float* __restrict__ log_dt, const float* __restrict__ log_w_real,
    const float* __restrict__ w_imag, const float* __restrict__ C_re,
    const float* __restrict__ C_im, int h, int n, int half)
{
    Consts K;
    const float dt = expf(log_dt[h]);                         // accurate: feeds ai
    const float wr = -__expf(log_w_real[h * NMODES + n]);     // fast: magnitude-only path
    const float wi = w_imag[h * NMODES + n];
    const float ar = wr * dt;
    const float ai = wi * dt;

    float s, c;
    const float ez = expf(ar);                                // accurate: amplified x2048
    sincosf(ai, &s, &c);                                      // accurate, small arg
    const float zr = ez * c, zi = ez * s;
    K.zr = zr; K.zi = zi;

    // 2*Cmod = 2*C*(z-1)/w  (division not amplified -> fast)
    const float inv = __fdividef(1.0f, wr * wr + wi * wi);
    const float zm  = zr - 1.0f;
    const float tr  = (zm * wr + zi * wi) * inv;
    const float ti  = (zi * wr - zm * wi) * inv;
    const float cre = C_re[h * NMODES + n];
    const float cim = C_im[h * NMODES + n];
    float ur = 2.0f * (cre * tr - cim * ti);
    float ui = 2.0f * (cre * ti + cim * tr);

    // squaring chain: z^2 ... z^1024 (no library calls)
    float pr = zr, pi = zi;
#define SQ_ { float t_ = pr * pr - pi * pi; pi = 2.0f * pr * pi; pr = t_; }
    SQ_ SQ_ SQ_ SQ_                       // z^16
    K.z16r = pr; K.z16i = pi;
    SQ_                                   // z^32
    K.z32r = pr; K.z32i = pi;
    SQ_                                   // z^64
    K.z64r = pr; K.z64i = pi;
    SQ_ SQ_ SQ_                           // z^512
    K.z512r = pr; K.z512i = pi;
    SQ_                                   // z^1024
#undef SQ_
    if (half) {                           // seed rows 16..31: x z^1024
        const float t = ur * pr - ui * pi;
        ui = ur * pi + ui * pr; ur = t;
    }
    K.u1r = ur; K.u1i = ui;
    return K;
}

__global__ __launch_bounds__(TPB, 4)
void ssd_tc_v10_kernel(
    const float* __restrict__ log_dt,
    const float* __restrict__ log_w_real,
    const float* __restrict__ w_imag,
    const float* __restrict__ C_re,
    const float* __restrict__ C_im,
    float* __restrict__ out)
{
    extern __shared__ __align__(16) char smem_raw[];
    const uint32_t aA = smem_u32(smem_raw);
    const uint32_t aB = aA + A_BYTES;

    const int tid  = threadIdx.x;
    const int lane = tid & 31;
    const int warp = tid >> 5;
    const int n    = tid & 63;     // mode (duplicated across halves)
    const int half = tid >> 6;     // 0/1
    const int r4   = lane >> 2;
    const int c4   = lane & 3;

    const int n3  = n & 3;
    const int kkn = n >> 2;            // this mode's k-group
    const uint32_t kxsA = (uint32_t)(kkn & 1) << 6;
    const uint32_t kxsB = (uint32_t)(kkn & 1) << 5;

    const int h0 = blockIdx.x * 2;
    Consts K = compute_consts(log_dt, log_w_real, w_imag, C_re, C_im, h0, n, half);

    #pragma unroll 1
    for (int rep = 0; rep < 2; rep++) {
        const int h = h0 + rep;

        // ---------- A fragments: dual chains rows (16*half+s, +8), step x z^64 ----------
        {
            float u1r = K.u1r, u1i = K.u1i;
            float u2r = u1r * K.z512r - u1i * K.z512i;   // rows +8
            float u2i = u1r * K.z512i + u1i * K.z512r;
            const uint32_t baseA = aA + (uint32_t)(kkn * 2 + half) * 512 + (uint32_t)n3 * 16;
            #pragma unroll
            for (int s = 0; s < 8; s++) {
                sts128((baseA + (uint32_t)s * 64) ^ kxsA,
                       tf32c(u1r), tf32c(u2r), tf32c(u1i), tf32c(u2i));
                float t = u1r * K.z64r - u1i * K.z64i; u1i = u1r * K.z64i + u1i * K.z64r; u1r = t;
                t       = u2r * K.z64r - u2i * K.z64i; u2i = u2r * K.z64i + u2i * K.z64r; u2r = t;
            }
        }

        // ---------- B fragments: dual chains b = 32*half + j and +16, step x z ----------
        {
            float v0r = 1.0f, v0i = 0.0f;
            if (half) { v0r = K.z32r; v0i = K.z32i; }
            float v1r = v0r * K.z16r - v0i * K.z16i;
            float v1i = v0r * K.z16i + v0i * K.z16r;
            const uint32_t baseB = aB + (uint32_t)kkn * 2048 + (uint32_t)(half * 4) * 256 + (uint32_t)n3 * 8;
            #pragma unroll
            for (int j = 0; j < 16; j++) {
                const uint32_t off = (uint32_t)(j >> 3) * 256 + ((uint32_t)(j & 7) << 5);
                sts64((baseB + off) ^ kxsB,        tf32c(v0r), tf32c(-v0i));
                sts64((baseB + off + 512) ^ kxsB,  tf32c(v1r), tf32c(-v1i));   // +2*256 (b+16)
                float t = v0r * K.zr - v0i * K.zi; v0i = v0r * K.zi + v0i * K.zr; v0r = t;
                t       = v1r * K.zr - v1i * K.zi; v1i = v1r * K.zi + v1i * K.zr; v1r = t;
            }
        }
        __syncthreads();

        // ---------- GEMM 32x64x128; warp w: n-cols [16w, 16w+16) ----------
        float acc[16];
        #pragma unroll
        for (int i = 0; i < 16; i++) acc[i] = 0.0f;

        const uint32_t rdA = aA + (uint32_t)lane * 16;
        const uint32_t rdB = aB + (uint32_t)(warp * 2) * 256 + (uint32_t)lane * 8;

        #pragma unroll
        for (int kk = 0; kk < 16; kk++) {
            const uint32_t swA = (uint32_t)(kk & 1) << 6;
            const uint32_t swB = (uint32_t)(kk & 1) << 5;

            uint32_t a00, a01, a02, a03, a10, a11, a12, a13;
            lds128((rdA ^ swA) + (uint32_t)kk * 1024,       a00, a01, a02, a03);
            lds128((rdA ^ swA) + (uint32_t)kk * 1024 + 512, a10, a11, a12, a13);

            uint32_t b00, b01, b10, b11;
            lds64((rdB ^ swB) + (uint32_t)kk * 2048,        b00, b01);
            lds64((rdB ^ swB) + (uint32_t)kk * 2048 + 256,  b10, b11);

            mma8(acc + 0,  a00, a01, a02, a03, b00, b01);
            mma8(acc + 4,  a00, a01, a02, a03, b10, b11);
            mma8(acc + 8,  a10, a11, a12, a13, b00, b01);
            mma8(acc + 12, a10, a11, a12, a13, b10, b11);
        }

        // ---------- store (l = 64*a + b) ----------
        float* op = out + (size_t)h * LLEN;
        #pragma unroll
        for (int mt = 0; mt < 2; mt++) {
            #pragma unroll
            for (int nt = 0; nt < 2; nt++) {
                const float* a = acc + (mt * 2 + nt) * 4;
                const int row = 16 * mt + r4;
                const int col = 16 * warp + 8 * nt + 2 * c4;
                *reinterpret_cast<float2*>(op + row * 64 + col)       = make_float2(a[0], a[1]);
                *reinterpret_cast<float2*>(op + (row + 8) * 64 + col) = make_float2(a[2], a[3]);
            }
        }

        // ---------- pipelined consts for next head (independent of GEMM/stores) ----------
        if (rep == 0)
            K = compute_consts(log_dt, log_w_real, w_imag, C_re, C_im, h0 + 1, n, half);

        __syncthreads();   // protect smem overwrite by next rep
    }
}

extern "C" void kernel_launch(void* const* d_in, const int* in_sizes, int n_in,
                              void* d_out, int out_size)
{
    const float* log_dt     = (const float*)d_in[0];
    const float* log_w_real = (const float*)d_in[1];
    const float* w_imag     = (const float*)d_in[2];
    const float* C_re       = (const float*)d_in[3];
    const float* C_im       = (const float*)d_in[4];
    float*       out        = (float*)d_out;

    cudaFuncSetAttribute(ssd_tc_v10_kernel,
                         cudaFuncAttributeMaxDynamicSharedMemorySize, SMEM_BYTES);
    ssd_tc_v10_kernel<<<GRID, TPB, SMEM_BYTES>>>(log_dt, log_w_real, w_imag, C_re, C_im, out);
}

// round 11
// speedup vs baseline: 1.2364x; 1.1532x over previous
#include <cuda_runtime.h>
#include <cstdint>

#define HH      1024
#define NMODES  64
#define LLEN    2048
#define TPB     128
#define GRID    1024         // 1 head per CTA

// smem (dynamic), per chunk of 32 modes (k=64):
//  Apack: kk(8) x [mt(2) x slot(8) x n3(4)] x 16B = 8 KB
//  Bpack: kk(8) x [nt(8) x slot(8) x n3(4)] x 8B = 16 KB
#define A_BYTES   8192
#define B_BYTES   16384
#define SMEM_BYTES (A_BYTES + B_BYTES)

__device__ __forceinline__ uint32_t smem_u32(const void* p) {
    uint32_t a;
    asm("{ .reg .u64 t; cvta.to.shared.u64 t, %1; cvt.u32.u64 %0, t; }" : "=r"(a) : "l"(p));
    return a;
}
__device__ __forceinline__ void sts128(uint32_t a, float x, float y, float z, float w) {
    asm volatile("st.shared.v4.b32 [%0],{%1,%2,%3,%4};" :: "r"(a), "f"(x), "f"(y), "f"(z), "f"(w) : "memory");
}
__device__ __forceinline__ void sts64(uint32_t a, float x, float y) {
    asm volatile("st.shared.v2.b32 [%0],{%1,%2};" :: "r"(a), "f"(x), "f"(y) : "memory");
}
__device__ __forceinline__ void lds128(uint32_t a, uint32_t& x, uint32_t& y, uint32_t& z, uint32_t& w) {
    asm volatile("ld.shared.v4.u32 {%0,%1,%2,%3},[%4];" : "=r"(x), "=r"(y), "=r"(z), "=r"(w) : "r"(a));
}
__device__ __forceinline__ void lds64(uint32_t a, uint32_t& x, uint32_t& y) {
    asm volatile("ld.shared.v2.u32 {%0,%1},[%2];" : "=r"(x), "=r"(y) : "r"(a));
}
__device__ __forceinline__ void mma8(float* d,
                                     uint32_t a0, uint32_t a1, uint32_t a2, uint32_t a3,
                                     uint32_t b0, uint32_t b1) {
    asm volatile(
        "mma.sync.aligned.m16n8k8.row.col.f32.tf32.tf32.f32 "
        "{%0,%1,%2,%3},{%4,%5,%6,%7},{%8,%9},{%0,%1,%2,%3};"
        : "+f"(d[0]), "+f"(d[1]), "+f"(d[2]), "+f"(d[3])
        : "r"(a0), "r"(a1), "r"(a2), "r"(a3), "r"(b0), "r"(b1));
}
__device__ __forceinline__ void cmul(float& xr, float& xi, float br, float bi) {
    const float t = xr * br - xi * bi;
    xi = xr * bi + xi * br;
    xr = t;
}

__global__ __launch_bounds__(TPB, 7)   // 7 CTAs/SM, 148*7=1036 >= 1024: single wave
void ssd_tc_v11_kernel(
    const float* __restrict__ log_dt,
    const float* __restrict__ log_w_real,
    const float* __restrict__ w_imag,
    const float* __restrict__ C_re,
    const float* __restrict__ C_im,
    float* __restrict__ out)
{
    extern __shared__ __align__(16) char smem_raw[];
    const uint32_t aA = smem_u32(smem_raw);
    const uint32_t aB = aA + A_BYTES;

    const int tid  = threadIdx.x;
    const int lane = tid & 31;
    const int warp = tid >> 5;
    const int m    = tid & 31;     // mode within chunk
    const int q    = tid >> 5;     // 0..3 : gen work split
    const int mt   = q & 1;        // A m-tile
    const int sh   = q >> 1;       // A slot half
    const int r4   = lane >> 2;
    const int c4   = lane & 3;

    const int kkg = m >> 2;        // this mode's k-group (0..7)
    const int n3  = m & 3;
    const uint32_t kxA = (uint32_t)(kkg & 1) << 6;
    const uint32_t kxB = (uint32_t)(kkg & 3) << 5;

    const int h = blockIdx.x;
    const float dt = expf(log_dt[h]);    // per-head, once

    float acc[16];
    #pragma unroll
    for (int i = 0; i < 16; i++) acc[i] = 0.0f;

    #pragma unroll 1
    for (int c = 0; c < 2; c++) {
        const int n = c * 32 + m;

        // ---------- consts for this thread's mode ----------
        const float wr = -__expf(log_w_real[h * NMODES + n]);
        const float wi = w_imag[h * NMODES + n];
        const float ar = wr * dt;
        const float ai = wi * dt;

        float sn, cs;
        const float ez = expf(ar);               // accurate: amplified along chain
        sincosf(ai, &sn, &cs);                   // accurate, small arg
        const float zr = ez * cs, zi = ez * sn;

        // 2*Cmod = 2*C*(z-1)/w
        const float inv = __fdividef(1.0f, wr * wr + wi * wi);
        const float zm  = zr - 1.0f;
        const float tr  = (zm * wr + zi * wi) * inv;
        const float ti  = (zi * wr - zm * wi) * inv;
        const float cre = C_re[h * NMODES + n];
        const float cim = C_im[h * NMODES + n];
        float ur = 2.0f * (cre * tr - cim * ti);
        float ui = 2.0f * (cre * ti + cim * tr);

        // squaring chain z^2 .. z^1024
        float pr = zr, pi = zi;
#define SQ_ { const float t_ = pr * pr - pi * pi; pi = 2.0f * pr * pi; pr = t_; }
        SQ_ SQ_ SQ_                                   // z^8
        const float z8r = pr, z8i = pi;
        SQ_                                           // z^16
        const float z16r = pr, z16i = pi;
        SQ_                                           // z^32
        const float z32r = pr, z32i = pi;
        SQ_                                           // z^64
        const float z64r = pr, z64i = pi;
        SQ_ SQ_                                       // z^256
        const float z256r = pr, z256i = pi;
        SQ_                                           // z^512
        const float z512r = pr, z512i = pi;
        SQ_                                           // z^1024
#undef SQ_
        // ---------- A fragments: rows (16mt + 4sh + t, +8), step x z^64 ----------
        {
            float u1r = ur, u1i = ui;
            if (mt) cmul(u1r, u1i, pr, pi);          // x z^1024
            if (sh) cmul(u1r, u1i, z256r, z256i);    // x z^256
            float u2r = u1r, u2i = u1i;
            cmul(u2r, u2i, z512r, z512i);            // rows +8
            const uint32_t baseA = aA + (uint32_t)kkg * 1024 + (uint32_t)mt * 512 + (uint32_t)n3 * 16;
            #pragma unroll
            for (int t = 0; t < 4; t++) {
                const uint32_t s = (uint32_t)(4 * sh + t);
                sts128(baseA + ((s * 64) ^ kxA), u1r, u2r, u1i, u2i);
                cmul(u1r, u1i, z64r, z64i);
                cmul(u2r, u2i, z64r, z64i);
            }
        }

        // ---------- B fragments: b = 16q + j (+8), step x z ----------
        {
            float v0r = 1.0f, v0i = 0.0f;
            if (q & 1) cmul(v0r, v0i, z16r, z16i);
            if (q & 2) cmul(v0r, v0i, z32r, z32i);   // z^(16q)
            float v1r = v0r, v1i = v0i;
            cmul(v1r, v1i, z8r, z8i);                // b + 8
            const uint32_t baseB = aB + (uint32_t)kkg * 2048 + (uint32_t)(2 * q) * 256 + (uint32_t)n3 * 8;
            #pragma unroll
            for (int j = 0; j < 8; j++) {
                const uint32_t so = ((uint32_t)j * 32) ^ kxB;
                sts64(baseB + so,       v0r, -v0i);
                sts64(baseB + so + 256, v1r, -v1i);
                cmul(v0r, v0i, zr, zi);
                cmul(v1r, v1i, zr, zi);
            }
        }
        __syncthreads();

        // ---------- GEMM chunk: 8 kk, accumulate ----------
        const uint32_t rdA = aA + (uint32_t)lane * 16;
        const uint32_t rdB = aB + (uint32_t)warp * 512 + (uint32_t)lane * 8;

        #pragma unroll
        for (int kk = 0; kk < 8; kk++) {
            const uint32_t swA = (uint32_t)(kk & 1) << 6;
            const uint32_t swB = (uint32_t)(kk & 3) << 5;

            uint32_t a00, a01, a02, a03, a10, a11, a12, a13;
            lds128((rdA ^ swA) + (uint32_t)kk * 1024,       a00, a01, a02, a03);
            lds128((rdA ^ swA) + (uint32_t)kk * 1024 + 512, a10, a11, a12, a13);

            uint32_t b00, b01, b10, b11;
            lds64((rdB ^ swB) + (uint32_t)kk * 2048,        b00, b01);
            lds64((rdB ^ swB) + (uint32_t)kk * 2048 + 256,  b10, b11);

            mma8(acc + 0,  a00, a01, a02, a03, b00, b01);
            mma8(acc + 4,  a00, a01, a02, a03, b10, b11);
            mma8(acc + 8,  a10, a11, a12, a13, b00, b01);
            mma8(acc + 12, a10, a11, a12, a13, b10, b11);
        }

        if (c == 0) __syncthreads();   // before chunk-1 gen overwrites smem
    }

    // ---------- store (l = 64*a + b) ----------
    float* op = out + (size_t)h * LLEN;
    #pragma unroll
    for (int m2 = 0; m2 < 2; m2++) {
        #pragma unroll
        for (int nt = 0; nt < 2; nt++) {
            const float* a = acc + (m2 * 2 + nt) * 4;
            const int row = 16 * m2 + r4;
            const int col = 16 * warp + 8 * nt + 2 * c4;
            *reinterpret_cast<float2*>(op + row * 64 + col)       = make_float2(a[0], a[1]);
            *reinterpret_cast<float2*>(op + (row + 8) * 64 + col) = make_float2(a[2], a[3]);
        }
    }
}

extern "C" void kernel_launch(void* const* d_in, const int* in_sizes, int n_in,
                              void* d_out, int out_size)
{
    const float* log_dt     = (const float*)d_in[0];
    const float* log_w_real = (const float*)d_in[1];
    const float* w_imag     = (const float*)d_in[2];
    const float* C_re       = (const float*)d_in[3];
    const float* C_im       = (const float*)d_in[4];
    float*       out        = (float*)d_out;

    cudaFuncSetAttribute(ssd_tc_v11_kernel,
                         cudaFuncAttributeMaxDynamicSharedMemorySize, SMEM_BYTES);
    ssd_tc_v11_kernel<<<GRID, TPB, SMEM_BYTES>>>(log_dt, log_w_real, w_imag, C_re, C_im, out);
}